// round 1
// baseline (speedup 1.0000x reference)
#include <cuda_runtime.h>

#define H      20
#define NEX    13
#define EMBD   3
#define FIN    3
#define FOUT   5
#define HIN    8
#define HID    10
#define BLK    128
#define FROW   (H*FIN)   // 60 floats of f per row

__global__ __launch_bounds__(BLK)
void airfit_kernel(const int*   __restrict__ e,
                   const float* __restrict__ f,
                   const float* __restrict__ emb,
                   const float* __restrict__ Wf,
                   const float* __restrict__ bf,
                   const float* __restrict__ W1,
                   const float* __restrict__ b1,
                   const float* __restrict__ W2,
                   const float* __restrict__ b2,
                   const float* __restrict__ Wo,
                   const float* __restrict__ bo,
                   float*       __restrict__ out,
                   int n)
{
    // padded shared tiles: rows padded to 12 floats (48B) => float4-aligned
    __shared__ float s_f[BLK][61];                    // 61: gcd(61,32)=1, conflict-free
    __shared__ __align__(16) float s_emb[NEX][4];
    __shared__ __align__(16) float s_W1[H][HIN][12];
    __shared__ __align__(16) float s_b1[H][12];
    __shared__ __align__(16) float s_W2[H][12];
    __shared__ float s_b2[H];
    __shared__ float s_Wo[H];

    const int tid = threadIdx.x;
    const long long b0 = (long long)blockIdx.x * BLK;
    const long long b  = b0 + tid;

    // ---- stage weights (uniform, small) ----
    for (int i = tid; i < NEX * EMBD; i += BLK) s_emb[i / EMBD][i % EMBD] = emb[i];
    if (tid < NEX) s_emb[tid][3] = 0.0f;
    for (int i = tid; i < H * HIN * HID; i += BLK) {
        int h = i / (HIN * HID), r = i % (HIN * HID);
        s_W1[h][r / HID][r % HID] = W1[i];
    }
    for (int i = tid; i < H * HID; i += BLK) {
        s_b1[i / HID][i % HID] = b1[i];
        s_W2[i / HID][i % HID] = W2[i];
    }
    if (tid < H) { s_b2[tid] = b2[tid]; s_Wo[tid] = Wo[tid]; }

    // ---- stage f through smem: coalesced float4 global reads ----
    {
        int rows = n - (int)b0;
        if (rows > BLK) rows = BLK;
        if (rows < 0)   rows = 0;
        const float4* fg = reinterpret_cast<const float4*>(f + b0 * FROW);
        const int nf4 = rows * (FROW / 4);            // 60 % 4 == 0
        for (int v = tid; v < nf4; v += BLK) {
            float4 val = fg[v];
            int fl  = v * 4;
            int row = fl / FROW;
            int col = fl % FROW;
            s_f[row][col + 0] = val.x;
            s_f[row][col + 1] = val.y;
            s_f[row][col + 2] = val.z;
            s_f[row][col + 3] = val.w;
        }
    }
    __syncthreads();

    if (b >= n) return;

    // feature Linear weights live in registers (warp-uniform __ldg, L1-broadcast)
    float wf[FIN][FOUT], bfr[FOUT];
#pragma unroll
    for (int i = 0; i < FIN; i++)
#pragma unroll
        for (int j = 0; j < FOUT; j++)
            wf[i][j] = __ldg(&Wf[i * FOUT + j]);
#pragma unroll
    for (int j = 0; j < FOUT; j++) bfr[j] = __ldg(&bf[j]);

    const int* eb = e + b * H;
    float acc = __ldg(bo);

#pragma unroll 2
    for (int h = 0; h < H; h++) {
        const int idx = __ldg(&eb[h]);
        const float4 ev = *reinterpret_cast<const float4*>(&s_emb[idx][0]);

        const float f0 = s_f[tid][h * 3 + 0];
        const float f1 = s_f[tid][h * 3 + 1];
        const float f2 = s_f[tid][h * 3 + 2];

        float x[HIN];
        x[0] = ev.x; x[1] = ev.y; x[2] = ev.z;
#pragma unroll
        for (int j = 0; j < FOUT; j++)
            x[3 + j] = fmaf(f2, wf[2][j], fmaf(f1, wf[1][j], fmaf(f0, wf[0][j], bfr[j])));

        // h1 = x @ W1[h] + b1[h], accumulated in 10 registers
        float4 t0 = *reinterpret_cast<const float4*>(&s_b1[h][0]);
        float4 t1 = *reinterpret_cast<const float4*>(&s_b1[h][4]);
        float2 t2 = *reinterpret_cast<const float2*>(&s_b1[h][8]);
#pragma unroll
        for (int i = 0; i < HIN; i++) {
            const float xi = x[i];
            const float4 w0 = *reinterpret_cast<const float4*>(&s_W1[h][i][0]);
            const float4 w1 = *reinterpret_cast<const float4*>(&s_W1[h][i][4]);
            const float2 w2 = *reinterpret_cast<const float2*>(&s_W1[h][i][8]);
            t0.x = fmaf(xi, w0.x, t0.x);
            t0.y = fmaf(xi, w0.y, t0.y);
            t0.z = fmaf(xi, w0.z, t0.z);
            t0.w = fmaf(xi, w0.w, t0.w);
            t1.x = fmaf(xi, w1.x, t1.x);
            t1.y = fmaf(xi, w1.y, t1.y);
            t1.z = fmaf(xi, w1.z, t1.z);
            t1.w = fmaf(xi, w1.w, t1.w);
            t2.x = fmaf(xi, w2.x, t2.x);
            t2.y = fmaf(xi, w2.y, t2.y);
        }

        // leaky_relu (slope 0.01) then dot with W2[h]
        const float4 v0 = *reinterpret_cast<const float4*>(&s_W2[h][0]);
        const float4 v1 = *reinterpret_cast<const float4*>(&s_W2[h][4]);
        const float2 v2 = *reinterpret_cast<const float2*>(&s_W2[h][8]);
        #define LK(v) ((v) > 0.0f ? (v) : 0.01f * (v))
        float z = s_b2[h];
        z = fmaf(LK(t0.x), v0.x, z);
        z = fmaf(LK(t0.y), v0.y, z);
        z = fmaf(LK(t0.z), v0.z, z);
        z = fmaf(LK(t0.w), v0.w, z);
        z = fmaf(LK(t1.x), v1.x, z);
        z = fmaf(LK(t1.y), v1.y, z);
        z = fmaf(LK(t1.z), v1.z, z);
        z = fmaf(LK(t1.w), v1.w, z);
        z = fmaf(LK(t2.x), v2.x, z);
        z = fmaf(LK(t2.y), v2.y, z);
        #undef LK

        // softplus = max(z,0) + log1p(exp(-|z|)); fast-math version is
        // accurate because the log term only matters when it is O(1).
        const float sp = fmaxf(z, 0.0f) + __logf(1.0f + __expf(-fabsf(z)));

        acc = fmaf(sp, s_Wo[h], acc);
    }

    out[b] = acc;
}

extern "C" void kernel_launch(void* const* d_in, const int* in_sizes, int n_in,
                              void* d_out, int out_size)
{
    const int*   e   = (const int*)  d_in[0];
    const float* f   = (const float*)d_in[1];
    const float* emb = (const float*)d_in[2];
    const float* Wf  = (const float*)d_in[3];
    const float* bf  = (const float*)d_in[4];
    const float* W1  = (const float*)d_in[5];
    const float* b1  = (const float*)d_in[6];
    const float* W2  = (const float*)d_in[7];
    const float* b2  = (const float*)d_in[8];
    const float* Wo  = (const float*)d_in[9];
    const float* bo  = (const float*)d_in[10];
    float* out = (float*)d_out;

    const int n = in_sizes[0] / H;          // rows
    const int grid = (n + BLK - 1) / BLK;
    airfit_kernel<<<grid, BLK>>>(e, f, emb, Wf, bf, W1, b1, W2, b2, Wo, bo, out, n);
}